// round 1
// baseline (speedup 1.0000x reference)
#include <cuda_runtime.h>
#include <cstdint>
#include <cstdio>

// ============================================================================
// myVMLSTMCell fused low-rank LSTM cell, fp32 baseline with f32x2 packed FMA.
//
// Math restructure:
//   Stage A (pack):  build merged expansion weights W[kappa][192][1024] where
//       kappa in {i,f,o,n}: kk<64 -> Vx col (kappa*1024+j), kk in [64,128) ->
//       Vh_0[g][kk-64][mh], kk in [128,192) -> Vh_1, with g = kappa>>1,
//       mh = ((kappa^1)&1)*1024 + j.  Also coef_x, coef_h (permuted), bias sum.
//   Stage B: A_cat[b][320] = [P(64) | T0g0 T1g0 (128) | T0g1 T1g1 (128)]
//       P = x@Ux ; T_i[b,g,:] = h[b, ((g+i)%2) half] @ Uh_i[g]
//   Stage C: gacc[b][kappa][j] = dot(A-slice(g=kappa>>1), W[kappa][:][j]) (K=192)
//       fused epilogue: gates, c_next, h_next.
// ============================================================================

typedef unsigned long long ull;

#define NB 8192
#define NH 1024
#define KA 320
#define KW 192
#define ASTR 68                      // padded smem stride for A (float4-aligned)
#define SMEM_C_BYTES ((KA*ASTR + 4*KW*32)*4)

__device__ float g_A[NB*KA];         // 10.5 MB scratch
__device__ float g_W[4*KW*NH];       // 3 MB merged weights
__device__ float g_cx[4*NH];
__device__ float g_ch[4*NH];
__device__ float g_cb[4*NH];

// ---- f32x2 helpers (sm_103a packed dual-fp32) ------------------------------
__device__ __forceinline__ ull pk2(float lo, float hi) {
    ull r; asm("mov.b64 %0, {%1,%2};" : "=l"(r) : "f"(lo), "f"(hi)); return r;
}
__device__ __forceinline__ void upk2(ull v, float& lo, float& hi) {
    asm("mov.b64 {%0,%1}, %2;" : "=f"(lo), "=f"(hi) : "l"(v));
}
__device__ __forceinline__ void fma2(ull& d, ull a, ull b) {
    asm("fma.rn.f32x2 %0, %1, %2, %3;" : "=l"(d) : "l"(a), "l"(b), "l"(d));
}

// ============================================================================
// Kernel A1: pack merged expansion weights g_W[kappa][kk][j]
// ============================================================================
__global__ void pack_w_kernel(const float* __restrict__ Vx,
                              const float* __restrict__ Vh0,
                              const float* __restrict__ Vh1) {
    int idx = blockIdx.x * 256 + threadIdx.x;
    if (idx >= 4 * KW * NH) return;
    int j   = idx & 1023;
    int kk  = (idx >> 10) % KW;
    int kap = idx / (KW * NH);
    int g   = kap >> 1;
    int mh  = (((kap ^ 1) & 1) << 10) + j;   // h-path column within group
    float v;
    if (kk < 64)        v = Vx[(kap * NH + j) * 64 + kk];
    else if (kk < 128)  v = Vh0[g * 131072 + (kk - 64) * 2048 + mh];
    else                v = Vh1[g * 131072 + (kk - 128) * 2048 + mh];
    g_W[idx] = v;
}

// ============================================================================
// Kernel A2: coef_x (kappa order), coef_h (permuted kappa^1), combined bias
// ============================================================================
__global__ void coef_kernel(const float* __restrict__ Ux,
                            const float* __restrict__ Vx,
                            const float* __restrict__ Uh0,
                            const float* __restrict__ Vh0,
                            const float* __restrict__ bx,
                            const float* __restrict__ bh) {
    int idx = blockIdx.x * 256 + threadIdx.x;
    if (idx >= 4 * NH) return;
    int j = idx & 1023;
    int kap = idx >> 10;
    int g  = kap >> 1;
    int mh = (((kap ^ 1) & 1) << 10) + j;
    float sx = 0.f, sh = 0.f;
    #pragma unroll 8
    for (int r = 0; r < 64; r++) {
        sx += Ux[j * 64 + r] * Vx[(kap * NH + j) * 64 + r];
        sh += Uh0[j * 64 + r] * Vh0[g * 131072 + r * 2048 + mh];
    }
    g_cx[idx] = sx;
    g_ch[idx] = sh;
    g_cb[idx] = bx[(kap << 10) + j] + bh[((kap ^ 1) << 10) + j];
}

// ============================================================================
// Kernel B: stage-1 contractions -> g_A[b][320]
//   grid = (128 row-tiles, 10 column-blocks), 256 threads
//   cb 0,1: P halves (A=x, W=Ux, K=1024)
//   cb 2..9: (i,g,half) -> T_i[b][g][half*32..], K=512, A = h shifted
// ============================================================================
__global__ __launch_bounds__(256) void stage1_kernel(
        const float* __restrict__ x, const float* __restrict__ h,
        const float* __restrict__ Ux, const float* __restrict__ Uh0,
        const float* __restrict__ Uh1) {
    __shared__ float Xs[64 * ASTR];
    __shared__ float Ws[64 * 32];

    int cb = blockIdx.y;
    const float* Ap; const float* Wp;
    int K, noff, outoff, aoff;
    if (cb < 2) {
        Ap = x; Wp = Ux; K = 1024; noff = cb * 32; outoff = cb * 32; aoff = 0;
    } else {
        int e = cb - 2;
        int i = e >> 2, g = (e >> 1) & 1, half = e & 1;
        Ap = h; Wp = (i ? Uh1 : Uh0) + g * 512 * 64;
        K = 512; noff = half * 32;
        outoff = 64 + g * 128 + i * 64 + half * 32;
        aoff = ((g + i) & 1) * 512;
    }
    int tid = threadIdx.x, tx = tid & 31, ty = tid >> 5;
    int b0 = blockIdx.x * 64;

    ull acc[4] = {0ull, 0ull, 0ull, 0ull};

    for (int k0 = 0; k0 < K; k0 += 64) {
        for (int i2 = tid; i2 < 64 * 64; i2 += 256) {
            int r = i2 >> 6, kk = i2 & 63;
            Xs[kk * ASTR + r] = Ap[(size_t)(b0 + r) * NH + aoff + k0 + kk];
        }
        for (int i2 = tid; i2 < 64 * 32; i2 += 256) {
            int kk = i2 >> 5, n = i2 & 31;
            Ws[kk * 32 + n] = Wp[(k0 + kk) * 64 + noff + n];
        }
        __syncthreads();
        #pragma unroll 8
        for (int kk = 0; kk < 64; kk++) {
            float w = Ws[kk * 32 + tx];
            ull w2 = pk2(w, w);
            const ulonglong2* ap =
                reinterpret_cast<const ulonglong2*>(&Xs[kk * ASTR + ty * 8]);
            ulonglong2 aA = ap[0], aB = ap[1];
            fma2(acc[0], aA.x, w2);
            fma2(acc[1], aA.y, w2);
            fma2(acc[2], aB.x, w2);
            fma2(acc[3], aB.y, w2);
        }
        __syncthreads();
    }
    #pragma unroll
    for (int p = 0; p < 4; p++) {
        float lo, hi; upk2(acc[p], lo, hi);
        int r = ty * 8 + p * 2;
        g_A[(size_t)(b0 + r) * KA + outoff + tx] = lo;
        g_A[(size_t)(b0 + r + 1) * KA + outoff + tx] = hi;
    }
}

// ============================================================================
// Kernel C: stage-2 merged expansion GEMM (K=192) + fused LSTM epilogue
//   grid = (32 j-tiles, 128 b-tiles), 256 threads, smem ~181 KB (1 block/SM)
//   thread: tx -> one j column, ty -> 8 batch rows (4 f32x2 pairs), 4 gates
// ============================================================================
__global__ __launch_bounds__(256, 1) void stage2_kernel(
        const float* __restrict__ x, const float* __restrict__ h,
        const float* __restrict__ c, const float* __restrict__ dia_x,
        const float* __restrict__ dia_h, float* __restrict__ out) {
    extern __shared__ float sm[];
    float* Asm = sm;               // [320][ASTR] transposed: Asm[kk*ASTR + b]
    float* Wsm = sm + KA * ASTR;   // [4][192][32]

    int j0 = blockIdx.x * 32;
    int b0 = blockIdx.y * 64;
    int tid = threadIdx.x, tx = tid & 31, ty = tid >> 5;

    for (int i2 = tid; i2 < 64 * KA; i2 += 256) {
        int b = i2 / KA, kk = i2 % KA;
        Asm[kk * ASTR + b] = g_A[(size_t)(b0 + b) * KA + kk];
    }
    for (int i2 = tid; i2 < 4 * KW * 32; i2 += 256) {
        int jj = i2 & 31;
        int kk = (i2 >> 5) % KW;
        int kap = i2 / (KW * 32);
        Wsm[i2] = g_W[kap * (KW * NH) + kk * NH + j0 + jj];
    }
    __syncthreads();

    ull acc[4][4];
    #pragma unroll
    for (int p = 0; p < 4; p++)
        #pragma unroll
        for (int k = 0; k < 4; k++) acc[p][k] = 0ull;

    // Phase 1: kk 0..63 — P rows, shared by both groups
    #pragma unroll 4
    for (int kk = 0; kk < 64; kk++) {
        float w0s = Wsm[(0 * KW + kk) * 32 + tx];
        float w1s = Wsm[(1 * KW + kk) * 32 + tx];
        float w2s = Wsm[(2 * KW + kk) * 32 + tx];
        float w3s = Wsm[(3 * KW + kk) * 32 + tx];
        ull w0 = pk2(w0s, w0s), w1 = pk2(w1s, w1s);
        ull w2 = pk2(w2s, w2s), w3 = pk2(w3s, w3s);
        const ulonglong2* ap =
            reinterpret_cast<const ulonglong2*>(&Asm[kk * ASTR + ty * 8]);
        ulonglong2 aA = ap[0], aB = ap[1];
        ull a[4] = {aA.x, aA.y, aB.x, aB.y};
        #pragma unroll
        for (int p = 0; p < 4; p++) {
            fma2(acc[p][0], a[p], w0);
            fma2(acc[p][1], a[p], w1);
            fma2(acc[p][2], a[p], w2);
            fma2(acc[p][3], a[p], w3);
        }
    }
    // Phase 2: kk 64..191 — group0 slice at row kk, group1 at row kk+128
    #pragma unroll 2
    for (int kk = 64; kk < 192; kk++) {
        float w0s = Wsm[(0 * KW + kk) * 32 + tx];
        float w1s = Wsm[(1 * KW + kk) * 32 + tx];
        float w2s = Wsm[(2 * KW + kk) * 32 + tx];
        float w3s = Wsm[(3 * KW + kk) * 32 + tx];
        ull w0 = pk2(w0s, w0s), w1 = pk2(w1s, w1s);
        ull w2 = pk2(w2s, w2s), w3 = pk2(w3s, w3s);
        const ulonglong2* ap0 =
            reinterpret_cast<const ulonglong2*>(&Asm[kk * ASTR + ty * 8]);
        const ulonglong2* ap1 =
            reinterpret_cast<const ulonglong2*>(&Asm[(kk + 128) * ASTR + ty * 8]);
        ulonglong2 aA0 = ap0[0], aB0 = ap0[1];
        ulonglong2 aA1 = ap1[0], aB1 = ap1[1];
        ull a0[4] = {aA0.x, aA0.y, aB0.x, aB0.y};
        ull a1[4] = {aA1.x, aA1.y, aB1.x, aB1.y};
        #pragma unroll
        for (int p = 0; p < 4; p++) {
            fma2(acc[p][0], a0[p], w0);
            fma2(acc[p][1], a0[p], w1);
            fma2(acc[p][2], a1[p], w2);
            fma2(acc[p][3], a1[p], w3);
        }
    }

    // Fused epilogue
    int j = j0 + tx;
    float dx = dia_x[j], dh = dia_h[j];
    float cx[4], ch[4], cbv[4];
    #pragma unroll
    for (int k = 0; k < 4; k++) {
        cx[k]  = g_cx[(k << 10) + j];
        ch[k]  = g_ch[(k << 10) + j];
        cbv[k] = g_cb[(k << 10) + j];
    }
    #pragma unroll
    for (int p = 0; p < 4; p++) {
        float g0l, g0h, g1l, g1h, g2l, g2h, g3l, g3h;
        upk2(acc[p][0], g0l, g0h);
        upk2(acc[p][1], g1l, g1h);
        upk2(acc[p][2], g2l, g2h);
        upk2(acc[p][3], g3l, g3h);
        float ga[2][4] = {{g0l, g1l, g2l, g3l}, {g0h, g1h, g2h, g3h}};
        #pragma unroll
        for (int e = 0; e < 2; e++) {
            int b = b0 + ty * 8 + p * 2 + e;
            size_t off = (size_t)b * NH + j;
            float xv = x[off], hv = h[off], cv = c[off];
            float base = dx * xv + dh * hv;
            float v0 = ga[e][0] - xv * cx[0] - hv * ch[0] + cbv[0] + base; // i
            float v1 = ga[e][1] - xv * cx[1] - hv * ch[1] + cbv[1] + base; // f
            float v2 = ga[e][2] - xv * cx[2] - hv * ch[2] + cbv[2] + base; // o
            float v3 = ga[e][3] - xv * cx[3] - hv * ch[3] + cbv[3] + base; // n
            float ig = 1.f / (1.f + expf(-v0));
            float fg = 1.f / (1.f + expf(-v1));
            float og = 1.f / (1.f + expf(-v2));
            float ng = tanhf(v3);
            float cn = fg * cv + ig * ng;
            float hn = og * tanhf(cn);
            out[off] = hn;
            out[(size_t)NB * NH + off] = cn;
        }
    }
}

// ============================================================================
extern "C" void kernel_launch(void* const* d_in, const int* in_sizes, int n_in,
                              void* d_out, int out_size) {
    const float* x     = (const float*)d_in[0];
    const float* h     = (const float*)d_in[1];
    const float* c     = (const float*)d_in[2];
    const float* dia_x = (const float*)d_in[3];
    const float* dia_h = (const float*)d_in[4];
    const float* Ux    = (const float*)d_in[5];
    const float* Vx    = (const float*)d_in[6];
    const float* Uh0   = (const float*)d_in[7];
    const float* Vh0   = (const float*)d_in[8];
    const float* Uh1   = (const float*)d_in[9];
    const float* Uh1V  = (const float*)d_in[10];  // Vh_1
    const float* bx    = (const float*)d_in[11];
    const float* bh    = (const float*)d_in[12];
    float* out = (float*)d_out;

    cudaFuncSetAttribute(stage2_kernel,
                         cudaFuncAttributeMaxDynamicSharedMemorySize,
                         SMEM_C_BYTES);

    pack_w_kernel<<<(4 * KW * NH + 255) / 256, 256>>>(Vx, Vh0, Uh1V);
    coef_kernel<<<16, 256>>>(Ux, Vx, Uh0, Vh0, bx, bh);
    stage1_kernel<<<dim3(128, 10), 256>>>(x, h, Ux, Uh0, Uh1);
    stage2_kernel<<<dim3(32, 128), 256, SMEM_C_BYTES>>>(x, h, c, dia_x, dia_h,
                                                        out);
}

// round 2
// speedup vs baseline: 1.9148x; 1.9148x over previous
#include <cuda_runtime.h>
#include <cstdint>

// ============================================================================
// myVMLSTMCell fused low-rank LSTM cell — fp32, f32x2 packed FMA, big tiles.
//
//   Stage A: pack merged expansion weights W[kappa][192][1024]; coef/bias.
//   Stage B: A_cat[320][b] (TRANSPOSED scratch) = [P(64)|T0g0 T1g0|T0g1 T1g1]
//   Stage C: K=192 expansion GEMM (8b x 4j x 4gates per thread) + LSTM epilogue
// ============================================================================

typedef unsigned long long ull;

#define NB 8192
#define NH 1024
#define KA 320
#define KW 192
#define S2_SMEM ((KA*64 + 32*4*128)*4)   // 147456 B

__device__ float g_AT[KA*NB];        // transposed scratch [col][b], 10.5 MB
__device__ float g_W[4*KW*NH];       // merged weights, 3 MB
__device__ float g_cx[4*NH];
__device__ float g_ch[4*NH];
__device__ float g_cb[4*NH];

// ---- f32x2 helpers ---------------------------------------------------------
__device__ __forceinline__ ull pk2(float lo, float hi) {
    ull r; asm("mov.b64 %0, {%1,%2};" : "=l"(r) : "f"(lo), "f"(hi)); return r;
}
__device__ __forceinline__ void upk2(ull v, float& lo, float& hi) {
    asm("mov.b64 {%0,%1}, %2;" : "=f"(lo), "=f"(hi) : "l"(v));
}
__device__ __forceinline__ void fma2(ull& d, ull a, ull b) {
    asm("fma.rn.f32x2 %0, %1, %2, %3;" : "=l"(d) : "l"(a), "l"(b), "l"(d));
}
__device__ __forceinline__ float sigm_f(float v) {
    return __fdividef(1.f, 1.f + __expf(-v));
}
__device__ __forceinline__ float tanh_f(float v) {
    return 1.f - __fdividef(2.f, 1.f + __expf(2.f * v));
}

// ============================================================================
// Kernel A1: pack merged expansion weights g_W[kappa][kk][j]
// ============================================================================
__global__ void pack_w_kernel(const float* __restrict__ Vx,
                              const float* __restrict__ Vh0,
                              const float* __restrict__ Vh1) {
    int idx = blockIdx.x * 256 + threadIdx.x;
    if (idx >= 4 * KW * NH) return;
    int j   = idx & 1023;
    int kk  = (idx >> 10) % KW;
    int kap = idx / (KW * NH);
    int g   = kap >> 1;
    int mh  = (((kap ^ 1) & 1) << 10) + j;
    float v;
    if (kk < 64)        v = Vx[(kap * NH + j) * 64 + kk];
    else if (kk < 128)  v = Vh0[g * 131072 + (kk - 64) * 2048 + mh];
    else                v = Vh1[g * 131072 + (kk - 128) * 2048 + mh];
    g_W[idx] = v;
}

// ============================================================================
// Kernel A2: coef_x, coef_h (permuted), combined bias
// ============================================================================
__global__ void coef_kernel(const float* __restrict__ Ux,
                            const float* __restrict__ Vx,
                            const float* __restrict__ Uh0,
                            const float* __restrict__ Vh0,
                            const float* __restrict__ bx,
                            const float* __restrict__ bh) {
    int idx = blockIdx.x * 256 + threadIdx.x;
    if (idx >= 4 * NH) return;
    int j = idx & 1023;
    int kap = idx >> 10;
    int g  = kap >> 1;
    int mh = (((kap ^ 1) & 1) << 10) + j;
    float sx = 0.f, sh = 0.f;
    #pragma unroll 8
    for (int r = 0; r < 64; r++) {
        sx += Ux[j * 64 + r] * Vx[(kap * NH + j) * 64 + r];
        sh += Uh0[j * 64 + r] * Vh0[g * 131072 + r * 2048 + mh];
    }
    g_cx[idx] = sx;
    g_ch[idx] = sh;
    g_cb[idx] = bx[(kap << 10) + j] + bh[((kap ^ 1) << 10) + j];
}

// ============================================================================
// Kernel B: stage-1 contractions -> g_AT[col][b]   (transposed write)
//   grid (64 b-tiles of 128, 10 col-blocks), 256 threads
//   thread: tx = n lane (32 cols), ty in [0,8) -> 16 b rows (8 f32x2 pairs)
// ============================================================================
__global__ __launch_bounds__(256) void stage1_kernel(
        const float* __restrict__ x, const float* __restrict__ h,
        const float* __restrict__ Ux, const float* __restrict__ Uh0,
        const float* __restrict__ Uh1) {
    __shared__ float Xs[64 * 132];   // [kk][b0..127] pad 132
    __shared__ float Ws[64 * 32];

    int cb = blockIdx.y;
    const float* Ap; const float* Wp;
    int K, noff, outoff, aoff;
    if (cb < 2) {
        Ap = x; Wp = Ux; K = 1024; noff = cb * 32; outoff = cb * 32; aoff = 0;
    } else {
        int e = cb - 2;
        int i = e >> 2, g = (e >> 1) & 1, half = e & 1;
        Ap = h; Wp = (i ? Uh1 : Uh0) + g * 512 * 64;
        K = 512; noff = half * 32;
        outoff = 64 + g * 128 + i * 64 + half * 32;
        aoff = ((g + i) & 1) * 512;
    }
    int tid = threadIdx.x, tx = tid & 31, ty = tid >> 5;
    int b0 = blockIdx.x * 128;

    ull acc[8];
    #pragma unroll
    for (int p = 0; p < 8; p++) acc[p] = 0ull;

    for (int k0 = 0; k0 < K; k0 += 64) {
        // load X tile (transpose): 128 rows x 64 kk
        #pragma unroll
        for (int i2 = 0; i2 < 8; i2++) {
            int idx = tid + i2 * 256;           // 2048 float4
            int r = idx >> 4, c4 = idx & 15;
            float4 v = *(const float4*)&Ap[(size_t)(b0 + r) * NH + aoff + k0 + c4 * 4];
            Xs[(c4 * 4 + 0) * 132 + r] = v.x;
            Xs[(c4 * 4 + 1) * 132 + r] = v.y;
            Xs[(c4 * 4 + 2) * 132 + r] = v.z;
            Xs[(c4 * 4 + 3) * 132 + r] = v.w;
        }
        #pragma unroll
        for (int i2 = 0; i2 < 8; i2++) {
            int idx = tid + i2 * 256;
            int kk = idx >> 5, n = idx & 31;
            Ws[kk * 32 + n] = Wp[(size_t)(k0 + kk) * 64 + noff + n];
        }
        __syncthreads();
        #pragma unroll 8
        for (int kk = 0; kk < 64; kk++) {
            float w = Ws[kk * 32 + tx];
            ull uw = pk2(w, w);
            const ulonglong2* ar =
                (const ulonglong2*)&Xs[kk * 132 + ty * 16];   // broadcast
            ulonglong2 aA = ar[0], aB = ar[1], aC = ar[2], aD = ar[3];
            fma2(acc[0], aA.x, uw); fma2(acc[1], aA.y, uw);
            fma2(acc[2], aB.x, uw); fma2(acc[3], aB.y, uw);
            fma2(acc[4], aC.x, uw); fma2(acc[5], aC.y, uw);
            fma2(acc[6], aD.x, uw); fma2(acc[7], aD.y, uw);
        }
        __syncthreads();
    }

    // transpose via smem -> coalesced STG to g_AT[col][b]
    float* Ts = Xs;   // reuse, stride 129 (conflict-free)
    #pragma unroll
    for (int p = 0; p < 8; p++) {
        float lo, hi; upk2(acc[p], lo, hi);
        Ts[tx * 129 + ty * 16 + 2 * p]     = lo;
        Ts[tx * 129 + ty * 16 + 2 * p + 1] = hi;
    }
    __syncthreads();
    {
        int n = tid >> 3, boff = (tid & 7) * 16;
        #pragma unroll
        for (int q4 = 0; q4 < 4; q4++) {
            float4 v;
            v.x = Ts[n * 129 + boff + q4 * 4 + 0];
            v.y = Ts[n * 129 + boff + q4 * 4 + 1];
            v.z = Ts[n * 129 + boff + q4 * 4 + 2];
            v.w = Ts[n * 129 + boff + q4 * 4 + 3];
            *(float4*)&g_AT[(size_t)(outoff + n) * NB + b0 + boff + q4 * 4] = v;
        }
    }
}

// ============================================================================
// Kernel C: stage-2 expansion GEMM (K=192) + fused LSTM epilogue
//   block: 64 b x 128 j, grid (8, 128), 256 threads, smem 147 KB
//   thread: tx -> 4 j (2 f32x2 pairs), ty -> 8 b rows; 4 gates
//   acc[8b][4gate][2jp] = 128 fp32 accumulators as 64 x f32x2
// ============================================================================
__global__ __launch_bounds__(256, 1) void stage2_kernel(
        const float* __restrict__ x, const float* __restrict__ h,
        const float* __restrict__ c, const float* __restrict__ dia_x,
        const float* __restrict__ dia_h, float* __restrict__ out) {
    extern __shared__ float sm[];
    float* Asm = sm;                 // [320][64]  (kk-major, b contiguous)
    float* Wsm = sm + KA * 64;       // [32][4][128] per chunk

    int j0 = blockIdx.x * 128;
    int b0 = blockIdx.y * 64;
    int tid = threadIdx.x, tx = tid & 31, ty = tid >> 5;

    // load A tile from g_AT (coalesced, conflict-free smem writes)
    {
        float4* A4 = (float4*)Asm;
        const float4* G4 = (const float4*)g_AT;
        #pragma unroll
        for (int i2 = 0; i2 < 20; i2++) {
            int idx = tid + i2 * 256;           // 5120 float4
            int kk = idx >> 4, off = idx & 15;
            A4[kk * 16 + off] = G4[(size_t)kk * (NB / 4) + (b0 >> 2) + off];
        }
    }

    ull acc[8][4][2];
    #pragma unroll
    for (int b = 0; b < 8; b++)
        #pragma unroll
        for (int g = 0; g < 4; g++) { acc[b][g][0] = 0ull; acc[b][g][1] = 0ull; }

    const ulonglong2* Wv = (const ulonglong2*)Wsm;

    for (int ch = 0; ch < 6; ch++) {
        __syncthreads();
        // load W chunk [32 kk][4 gates][128 j]
        {
            float4* W4 = (float4*)Wsm;
            #pragma unroll
            for (int i2 = 0; i2 < 16; i2++) {
                int idx = tid + i2 * 256;       // 4096 float4
                int row = idx >> 5, off = idx & 31;   // row = kkL*4+g
                int kkL = row >> 2, g = row & 3;
                W4[row * 32 + off] =
                    *(const float4*)&g_W[(size_t)g * (KW * NH) +
                                         (ch * 32 + kkL) * NH + j0 + off * 4];
            }
        }
        __syncthreads();

        if (ch < 2) {
            // phase 1: P rows, shared by all gates
            #pragma unroll 2
            for (int kkL = 0; kkL < 32; kkL++) {
                int kk = ch * 32 + kkL;
                ulonglong2 w0 = Wv[(kkL * 4 + 0) * 32 + tx];
                ulonglong2 w1 = Wv[(kkL * 4 + 1) * 32 + tx];
                ulonglong2 w2 = Wv[(kkL * 4 + 2) * 32 + tx];
                ulonglong2 w3 = Wv[(kkL * 4 + 3) * 32 + tx];
                const float4* ar = (const float4*)&Asm[kk * 64 + ty * 8];
                float4 aA = ar[0], aB = ar[1];
                float av[8] = {aA.x, aA.y, aA.z, aA.w, aB.x, aB.y, aB.z, aB.w};
                #pragma unroll
                for (int b = 0; b < 8; b++) {
                    ull ua = pk2(av[b], av[b]);
                    fma2(acc[b][0][0], ua, w0.x); fma2(acc[b][0][1], ua, w0.y);
                    fma2(acc[b][1][0], ua, w1.x); fma2(acc[b][1][1], ua, w1.y);
                    fma2(acc[b][2][0], ua, w2.x); fma2(acc[b][2][1], ua, w2.y);
                    fma2(acc[b][3][0], ua, w3.x); fma2(acc[b][3][1], ua, w3.y);
                }
            }
        } else {
            // phase 2: gates 0,1 <- row kk (group0); gates 2,3 <- row kk+128
            #pragma unroll 2
            for (int kkL = 0; kkL < 32; kkL++) {
                int kk = ch * 32 + kkL;
                ulonglong2 w0 = Wv[(kkL * 4 + 0) * 32 + tx];
                ulonglong2 w1 = Wv[(kkL * 4 + 1) * 32 + tx];
                ulonglong2 w2 = Wv[(kkL * 4 + 2) * 32 + tx];
                ulonglong2 w3 = Wv[(kkL * 4 + 3) * 32 + tx];
                const float4* a0r = (const float4*)&Asm[kk * 64 + ty * 8];
                const float4* a1r = (const float4*)&Asm[(kk + 128) * 64 + ty * 8];
                float4 aA0 = a0r[0], aB0 = a0r[1];
                float4 aA1 = a1r[0], aB1 = a1r[1];
                float a0v[8] = {aA0.x, aA0.y, aA0.z, aA0.w,
                                aB0.x, aB0.y, aB0.z, aB0.w};
                float a1v[8] = {aA1.x, aA1.y, aA1.z, aA1.w,
                                aB1.x, aB1.y, aB1.z, aB1.w};
                #pragma unroll
                for (int b = 0; b < 8; b++) {
                    ull ua0 = pk2(a0v[b], a0v[b]);
                    ull ua1 = pk2(a1v[b], a1v[b]);
                    fma2(acc[b][0][0], ua0, w0.x); fma2(acc[b][0][1], ua0, w0.y);
                    fma2(acc[b][1][0], ua0, w1.x); fma2(acc[b][1][1], ua0, w1.y);
                    fma2(acc[b][2][0], ua1, w2.x); fma2(acc[b][2][1], ua1, w2.y);
                    fma2(acc[b][3][0], ua1, w3.x); fma2(acc[b][3][1], ua1, w3.y);
                }
            }
        }
    }

    // ---- fused LSTM epilogue -----------------------------------------------
    int j = j0 + tx * 4;
    float4 dxv = *(const float4*)&dia_x[j];
    float4 dhv = *(const float4*)&dia_h[j];
    float dx[4] = {dxv.x, dxv.y, dxv.z, dxv.w};
    float dh[4] = {dhv.x, dhv.y, dhv.z, dhv.w};
    float cx[4][4], chv[4][4], cb[4][4];
    #pragma unroll
    for (int k = 0; k < 4; k++) {
        float4 a = *(const float4*)&g_cx[(k << 10) + j];
        float4 bq = *(const float4*)&g_ch[(k << 10) + j];
        float4 cq = *(const float4*)&g_cb[(k << 10) + j];
        cx[k][0] = a.x;  cx[k][1] = a.y;  cx[k][2] = a.z;  cx[k][3] = a.w;
        chv[k][0] = bq.x; chv[k][1] = bq.y; chv[k][2] = bq.z; chv[k][3] = bq.w;
        cb[k][0] = cq.x; cb[k][1] = cq.y; cb[k][2] = cq.z; cb[k][3] = cq.w;
    }
    #pragma unroll
    for (int b = 0; b < 8; b++) {
        int row = b0 + ty * 8 + b;
        size_t off = (size_t)row * NH + j;
        float4 xv = *(const float4*)&x[off];
        float4 hv = *(const float4*)&h[off];
        float4 cv = *(const float4*)&c[off];
        float xa[4] = {xv.x, xv.y, xv.z, xv.w};
        float ha[4] = {hv.x, hv.y, hv.z, hv.w};
        float ca[4] = {cv.x, cv.y, cv.z, cv.w};
        float gg[4][4];
        #pragma unroll
        for (int g = 0; g < 4; g++) {
            float lo, hi;
            upk2(acc[b][g][0], lo, hi); gg[g][0] = lo; gg[g][1] = hi;
            upk2(acc[b][g][1], lo, hi); gg[g][2] = lo; gg[g][3] = hi;
        }
        float4 hn4, cn4;
        float hn[4], cn[4];
        #pragma unroll
        for (int jj = 0; jj < 4; jj++) {
            float base = dx[jj] * xa[jj] + dh[jj] * ha[jj];
            float v0 = gg[0][jj] - xa[jj] * cx[0][jj] - ha[jj] * chv[0][jj] + cb[0][jj] + base;
            float v1 = gg[1][jj] - xa[jj] * cx[1][jj] - ha[jj] * chv[1][jj] + cb[1][jj] + base;
            float v2 = gg[2][jj] - xa[jj] * cx[2][jj] - ha[jj] * chv[2][jj] + cb[2][jj] + base;
            float v3 = gg[3][jj] - xa[jj] * cx[3][jj] - ha[jj] * chv[3][jj] + cb[3][jj] + base;
            float ig = sigm_f(v0);
            float fg = sigm_f(v1);
            float og = sigm_f(v2);
            float ng = tanh_f(v3);
            float cnx = fg * ca[jj] + ig * ng;
            cn[jj] = cnx;
            hn[jj] = og * tanh_f(cnx);
        }
        hn4.x = hn[0]; hn4.y = hn[1]; hn4.z = hn[2]; hn4.w = hn[3];
        cn4.x = cn[0]; cn4.y = cn[1]; cn4.z = cn[2]; cn4.w = cn[3];
        *(float4*)&out[off] = hn4;
        *(float4*)&out[(size_t)NB * NH + off] = cn4;
    }
}

// ============================================================================
extern "C" void kernel_launch(void* const* d_in, const int* in_sizes, int n_in,
                              void* d_out, int out_size) {
    const float* x     = (const float*)d_in[0];
    const float* h     = (const float*)d_in[1];
    const float* c     = (const float*)d_in[2];
    const float* dia_x = (const float*)d_in[3];
    const float* dia_h = (const float*)d_in[4];
    const float* Ux    = (const float*)d_in[5];
    const float* Vx    = (const float*)d_in[6];
    const float* Uh0   = (const float*)d_in[7];
    const float* Vh0   = (const float*)d_in[8];
    const float* Uh1   = (const float*)d_in[9];
    const float* Vh1   = (const float*)d_in[10];
    const float* bx    = (const float*)d_in[11];
    const float* bh    = (const float*)d_in[12];
    float* out = (float*)d_out;

    cudaFuncSetAttribute(stage2_kernel,
                         cudaFuncAttributeMaxDynamicSharedMemorySize, S2_SMEM);

    pack_w_kernel<<<(4 * KW * NH + 255) / 256, 256>>>(Vx, Vh0, Vh1);
    coef_kernel<<<16, 256>>>(Ux, Vx, Uh0, Vh0, bx, bh);
    stage1_kernel<<<dim3(64, 10), 256>>>(x, h, Ux, Uh0, Uh1);
    stage2_kernel<<<dim3(8, 128), 256, S2_SMEM>>>(x, h, c, dia_x, dia_h, out);
}